// round 6
// baseline (speedup 1.0000x reference)
#include <cuda_runtime.h>
#include <cstdint>

#define NJ   23
#define NP   16
#define NT   128            // vertices per CTA (MMA M)
#define SBST 56             // sB row stride (floats): conflict-free for frag reads
#define SWST 128            // sW row stride (floats)
#define SDST 132            // sD row stride (floats): conflict-free frag stores

// dynamic smem (floats):
//   sB  [96 x SBST]   pose matrix B[k][n] (tf32-rounded)      5376 f
//   sW  [23 x SWST]   staged weights, transposed [j][vlocal]  2944 f
//   sT / sD (union)   P1 scratch (368*12=4416) / D stage (48*132=6336)
#define SB_OFF  0
#define SW_OFF  (96*SBST)
#define RC_OFF  (SW_OFF + NJ*SWST)
#define SMEM_FLOATS (RC_OFF + 48*SDST)
#define SMEM_BYTES  (SMEM_FLOATS * 4)

__constant__ float c_scale[NJ] = {
    0.78539816339744831f, 0.f, 0.f, 1.57079632679489662f, 1.57079632679489662f,
    0.78539816339744831f, 0.f, 0.78539816339744831f, 0.f, 0.78539816339744831f,
    0.f, 1.57079632679489662f, 1.57079632679489662f, 0.78539816339744831f, 0.f,
    0.78539816339744831f, 0.f, 0.78539816339744831f, 0.f, 0.f, 0.f, 0.f, 0.f };
__constant__ int c_slot[NJ] = {0,-1,-1,1,2,3,-1,4,-1,5,-1,6,7,8,-1,9,-1,10,-1,-1,-1,-1,-1};
__constant__ int c_par[NJ]  = {-1,0,1,1,3,4,5,4,7,4,9,1,11,12,13,12,15,12,17,0,19,0,21};

__device__ __forceinline__ float tf32r(float x) {   // round-to-nearest tf32 (unbiased)
    uint32_t r;
    asm("cvt.rna.tf32.f32 %0, %1;" : "=r"(r) : "f"(x));
    return __uint_as_float(r);
}
__device__ __forceinline__ uint32_t tf32u(float x) {
    uint32_t r;
    asm("cvt.rna.tf32.f32 %0, %1;" : "=r"(r) : "f"(x));
    return r;
}
__device__ __forceinline__ void mma8(float* d, uint32_t a0, uint32_t a1, uint32_t a2,
                                     uint32_t a3, uint32_t b0, uint32_t b1) {
    asm volatile(
        "mma.sync.aligned.m16n8k8.row.col.f32.tf32.tf32.f32 "
        "{%0,%1,%2,%3}, {%4,%5,%6,%7}, {%8,%9}, {%0,%1,%2,%3};"
        : "+f"(d[0]), "+f"(d[1]), "+f"(d[2]), "+f"(d[3])
        : "r"(a0), "r"(a1), "r"(a2), "r"(a3), "r"(b0), "r"(b1));
}

__global__ void __launch_bounds__(256, 2)
lbs_mma(const float* __restrict__ verts, const float* __restrict__ joints,
        const float* __restrict__ weights, const float* __restrict__ disp,
        const float* __restrict__ rdis,
        const float* jp0, const float* jp3, const float* jp4, const float* jp5,
        const float* jp7, const float* jp9, const float* jp11, const float* jp12,
        const float* jp13, const float* jp15, const float* jp17,
        float* __restrict__ out, float* __restrict__ out_joints, int V)
{
    extern __shared__ float sm[];
    float* sB = sm + SB_OFF;
    float* sW = sm + SW_OFF;
    float* sT = sm + RC_OFF;     // P1 scratch (local transforms), then reused as sD
    float* sD = sm + RC_OFF;

    const int tid  = threadIdx.x;
    const int wid  = tid >> 5;
    const int lane = tid & 31;
    const int g    = lane >> 2;   // groupID (row within fragment)
    const int tig  = lane & 3;    // threadID in group (col)
    const int v0   = blockIdx.x * NT;

    // ---- stage weights transposed: sW[j][vlocal] (coalesced gmem read) ----
    {
        int nv = V - v0; if (nv > NT) nv = NT;
        for (int t = tid; t < NT * NJ; t += 256) {
            int v = t / NJ, j = t - v * NJ;
            sW[j * SWST + v] = (v < nv) ? weights[(size_t)(v0 + v) * NJ + j] : 0.f;
        }
    }

    // ---- P1: local transforms T(p,jt) = [R | rel] into sT ----
    {
        const float* prm[11] = {jp0,jp3,jp4,jp5,jp7,jp9,jp11,jp12,jp13,jp15,jp17};
        for (int idx = tid; idx < NP * NJ; idx += 256) {
            int p = idx / NJ, jt = idx - p * NJ;
            float rx = 0.f, ry = 0.f, rz = 0.f;
            int s = c_slot[jt];
            if (s >= 0) {
                float sc = c_scale[jt];
                rx = sc * tanhf(prm[s][p*3+0]);
                ry = sc * tanhf(prm[s][p*3+1]);
                rz = sc * tanhf(prm[s][p*3+2]);
            }
            float ang = sqrtf(rx*rx + ry*ry + rz*rz + 1e-16f);
            float x = rx/ang, y = ry/ang, z = rz/ang;
            float sn = sinf(ang), cs = cosf(ang), t = 1.0f - cs;
            float* T = sT + idx * 12;
            T[0] = 1.f - t*(y*y+z*z); T[1] = -sn*z + t*x*y;     T[2] =  sn*y + t*x*z;
            T[3] =  sn*z + t*x*y;     T[4] = 1.f - t*(x*x+z*z); T[5] = -sn*x + t*y*z;
            T[6] = -sn*y + t*x*z;     T[7] =  sn*x + t*y*z;     T[8] = 1.f - t*(x*x+y*y);
            int par = c_par[jt];
            if (par < 0) { T[9]=joints[0]; T[10]=joints[1]; T[11]=joints[2]; }
            else {
                T[9]  = joints[jt*3+0] - joints[par*3+0];
                T[10] = joints[jt*3+1] - joints[par*3+1];
                T[11] = joints[jt*3+2] - joints[par*3+2];
            }
        }
    }
    __syncthreads();

    // ---- P2: per (p,jt) compose G along ancestor path; emit B rows (tf32) ----
    for (int idx = tid; idx < NP * NJ; idx += 256) {
        int p = idx / NJ, jt = idx - p * NJ;
        float shf[3];
#pragma unroll
        for (int k = 0; k < 3; k++)
            shf[k] = rdis[p*3+k] + 3.0f * tanhf(disp[p*3+k]);

        int chain[8], d = 0, a = jt;
        while (a >= 0) { chain[d++] = a; a = c_par[a]; }

        float G[12];
        {
            const float* Tr = sT + (p*NJ + chain[d-1]) * 12;
#pragma unroll
            for (int q = 0; q < 12; q++) G[q] = Tr[q];
        }
        for (int q = d - 2; q >= 0; q--) {
            const float* T = sT + (p*NJ + chain[q]) * 12;
            float N_[12];
#pragma unroll
            for (int i = 0; i < 3; i++) {
#pragma unroll
                for (int k = 0; k < 3; k++)
                    N_[i*3+k] = G[i*3]*T[k] + G[i*3+1]*T[3+k] + G[i*3+2]*T[6+k];
                N_[9+i] = G[i*3]*T[9] + G[i*3+1]*T[10] + G[i*3+2]*T[11] + G[9+i];
            }
#pragma unroll
            for (int q2 = 0; q2 < 12; q2++) G[q2] = N_[q2];
        }

        float jx = joints[jt*3], jy = joints[jt*3+1], jz = joints[jt*3+2];
#pragma unroll
        for (int i = 0; i < 3; i++) {
            float At = G[9+i] - (G[i*3]*jx + G[i*3+1]*jy + G[i*3+2]*jz) + shf[i];
            int n = 3*p + i;
            sB[(4*jt + 0)*SBST + n] = tf32r(G[i*3+0]);
            sB[(4*jt + 1)*SBST + n] = tf32r(G[i*3+1]);
            sB[(4*jt + 2)*SBST + n] = tf32r(G[i*3+2]);
            sB[(4*jt + 3)*SBST + n] = tf32r(At);
            if (blockIdx.x == 0)
                out_joints[(p*NJ + jt)*3 + i] = G[9+i] + shf[i];
        }
    }
    // zero-pad K rows 92..95
    if (tid < 192) {
        int r = 92 + tid / 48, c = tid % 48;
        sB[r * SBST + c] = 0.f;
    }
    __syncthreads();

    // ---- main: warp wid owns vertices [v0+16w, v0+16w+16); N=48, K=96 ----
    const int wbase = wid * 16 + g;          // local row of a0/a2 (vA); +8 for vB
    const int vA = v0 + wbase, vB = vA + 8;
    float cA[4] = {0.f, 0.f, 0.f, 1.f}, cBv[4] = {0.f, 0.f, 0.f, 1.f};
    if (vA < V) { cA[0]=verts[(size_t)vA*3]; cA[1]=verts[(size_t)vA*3+1]; cA[2]=verts[(size_t)vA*3+2]; }
    if (vB < V) { cBv[0]=verts[(size_t)vB*3]; cBv[1]=verts[(size_t)vB*3+1]; cBv[2]=verts[(size_t)vB*3+2]; }
    const float compA = cA[tig], compB = cBv[tig];

    float acc[6][4];
#pragma unroll
    for (int f = 0; f < 6; f++)
#pragma unroll
        for (int q = 0; q < 4; q++) acc[f][q] = 0.f;

    const uint32_t* sBu = (const uint32_t*)sB;
#pragma unroll
    for (int s = 0; s < 12; s++) {
        int j0 = 2*s, j1 = 2*s + 1;
        float w0A = sW[j0*SWST + wbase],     w0B = sW[j0*SWST + wbase + 8];
        float w1A = 0.f, w1B = 0.f;
        if (j1 < NJ) { w1A = sW[j1*SWST + wbase]; w1B = sW[j1*SWST + wbase + 8]; }
        uint32_t a0 = tf32u(w0A * compA);
        uint32_t a1 = tf32u(w0B * compB);
        uint32_t a2 = tf32u(w1A * compA);
        uint32_t a3 = tf32u(w1B * compB);
        int kr0 = (8*s + tig) * SBST + g;
        int kr1 = kr0 + 4 * SBST;
#pragma unroll
        for (int f = 0; f < 6; f++) {
            uint32_t b0 = sBu[kr0 + 8*f];
            uint32_t b1 = sBu[kr1 + 8*f];
            mma8(acc[f], a0, a1, a2, a3, b0, b1);
        }
    }

    // ---- stage D into smem (conflict-free) ----
    __syncthreads();   // sT no longer needed; sD overwrites region
#pragma unroll
    for (int f = 0; f < 6; f++) {
        int n0 = 8*f + 2*tig;
        sD[ n0      * SDST + wbase    ] = acc[f][0];
        sD[(n0 + 1) * SDST + wbase    ] = acc[f][1];
        sD[ n0      * SDST + wbase + 8] = acc[f][2];
        sD[(n0 + 1) * SDST + wbase + 8] = acc[f][3];
    }
    __syncthreads();

    // ---- epilogue: warp wid writes poses 2w, 2w+1; coalesced STG ----
#pragma unroll
    for (int pp = 0; pp < 2; pp++) {
        int p = wid * 2 + pp;
#pragma unroll
        for (int c = 0; c < 4; c++) {
            int vl = c * 32 + lane;
            int vg = v0 + vl;
            if (vg < V) {
                float o0 = sD[(3*p + 0) * SDST + vl];
                float o1 = sD[(3*p + 1) * SDST + vl];
                float o2 = sD[(3*p + 2) * SDST + vl];
                float* dst = out + ((size_t)p * V + vg) * 3;
                dst[0] = o0; dst[1] = o1; dst[2] = o2;
            }
        }
    }
}

// ---------------------------------------------------------------------------
extern "C" void kernel_launch(void* const* d_in, const int* in_sizes, int n_in,
                              void* d_out, int out_size)
{
    const float* verts   = (const float*)d_in[0];
    const float* joints  = (const float*)d_in[1];
    const float* weights = (const float*)d_in[2];
    const float* disp    = (const float*)d_in[3];
    const float* rdis    = (const float*)d_in[4];

    int V = in_sizes[0] / 3;
    float* out = (float*)d_out;
    float* out_joints = out + (size_t)out_size - (size_t)NP * NJ * 3;

    static bool attr_set = false;
    if (!attr_set) {
        cudaFuncSetAttribute(lbs_mma, cudaFuncAttributeMaxDynamicSharedMemorySize, SMEM_BYTES);
        attr_set = true;
    }

    int blocks = (V + NT - 1) / NT;
    lbs_mma<<<blocks, 256, SMEM_BYTES>>>(
        verts, joints, weights, disp, rdis,
        (const float*)d_in[5],  (const float*)d_in[6],  (const float*)d_in[7],
        (const float*)d_in[8],  (const float*)d_in[9],  (const float*)d_in[10],
        (const float*)d_in[11], (const float*)d_in[12], (const float*)d_in[13],
        (const float*)d_in[14], (const float*)d_in[15],
        out, out_joints, V);
}

// round 9
// speedup vs baseline: 2.5220x; 2.5220x over previous
#include <cuda_runtime.h>
#include <cstdint>

#define NJ   23
#define NP   16
#define NT   256            // vertices per CTA (MMA M)
#define SBST 56             // sB row stride (floats): conflict-free frag reads
#define SWST 257            // sW row stride: >= NT (rows disjoint!), odd -> conflict-free
#define SDST 260            // sD row stride: conflict-free frag stores/reads

// dynamic smem (floats), sD aliases sB/sW after mainloop:
#define SB_OFF  0
#define SW_OFF  (96*SBST)                   // 5376
#define SD_FLOATS  (48*SDST)                // 12480  (> SW_OFF + NJ*SWST = 11287)
#define SMEM_FLOATS SD_FLOATS
#define SMEM_BYTES (SMEM_FLOATS*4)          // 49920

__device__ __align__(16) float d_B[96*48];  // pose matrix B[k][n], tf32-rounded

__constant__ float c_scale[NJ] = {
    0.78539816339744831f, 0.f, 0.f, 1.57079632679489662f, 1.57079632679489662f,
    0.78539816339744831f, 0.f, 0.78539816339744831f, 0.f, 0.78539816339744831f,
    0.f, 1.57079632679489662f, 1.57079632679489662f, 0.78539816339744831f, 0.f,
    0.78539816339744831f, 0.f, 0.78539816339744831f, 0.f, 0.f, 0.f, 0.f, 0.f };
__constant__ int c_slot[NJ] = {0,-1,-1,1,2,3,-1,4,-1,5,-1,6,7,8,-1,9,-1,10,-1,-1,-1,-1,-1};
__constant__ int c_par[NJ]  = {-1,0,1,1,3,4,5,4,7,4,9,1,11,12,13,12,15,12,17,0,19,0,21};

__device__ __forceinline__ float tf32r(float x) {
    uint32_t r; asm("cvt.rna.tf32.f32 %0, %1;" : "=r"(r) : "f"(x));
    return __uint_as_float(r);
}
__device__ __forceinline__ uint32_t tf32u(float x) {
    uint32_t r; asm("cvt.rna.tf32.f32 %0, %1;" : "=r"(r) : "f"(x));
    return r;
}
__device__ __forceinline__ void mma8(float* d, uint32_t a0, uint32_t a1, uint32_t a2,
                                     uint32_t a3, uint32_t b0, uint32_t b1) {
    asm volatile(
        "mma.sync.aligned.m16n8k8.row.col.f32.tf32.tf32.f32 "
        "{%0,%1,%2,%3}, {%4,%5,%6,%7}, {%8,%9}, {%0,%1,%2,%3};"
        : "+f"(d[0]), "+f"(d[1]), "+f"(d[2]), "+f"(d[3])
        : "r"(a0), "r"(a1), "r"(a2), "r"(a3), "r"(b0), "r"(b1));
}

// ---------------------------------------------------------------------------
// Kernel 1: pose chain -> d_B (96x48 tf32) + out_joints. One block, 384 thr.
// ---------------------------------------------------------------------------
__global__ void pose_kernel(const float* __restrict__ joints,
                            const float* __restrict__ disp,
                            const float* __restrict__ rdis,
                            const float* jp0, const float* jp3, const float* jp4,
                            const float* jp5, const float* jp7, const float* jp9,
                            const float* jp11, const float* jp12, const float* jp13,
                            const float* jp15, const float* jp17,
                            float* __restrict__ out_joints)
{
    __shared__ float sT[NP*NJ*12];
    const int tid = threadIdx.x;

    if (tid < NP*NJ) {
        const float* prm[11] = {jp0,jp3,jp4,jp5,jp7,jp9,jp11,jp12,jp13,jp15,jp17};
        int p = tid / NJ, jt = tid - p*NJ;
        float rx = 0.f, ry = 0.f, rz = 0.f;
        int s = c_slot[jt];
        if (s >= 0) {
            float sc = c_scale[jt];
            rx = sc * tanhf(prm[s][p*3+0]);
            ry = sc * tanhf(prm[s][p*3+1]);
            rz = sc * tanhf(prm[s][p*3+2]);
        }
        float ang = sqrtf(rx*rx + ry*ry + rz*rz + 1e-16f);
        float x = rx/ang, y = ry/ang, z = rz/ang;
        float sn = sinf(ang), cs = cosf(ang), t = 1.0f - cs;
        float* T = sT + tid*12;
        T[0] = 1.f - t*(y*y+z*z); T[1] = -sn*z + t*x*y;     T[2] =  sn*y + t*x*z;
        T[3] =  sn*z + t*x*y;     T[4] = 1.f - t*(x*x+z*z); T[5] = -sn*x + t*y*z;
        T[6] = -sn*y + t*x*z;     T[7] =  sn*x + t*y*z;     T[8] = 1.f - t*(x*x+y*y);
        int par = c_par[jt];
        if (par < 0) { T[9]=joints[0]; T[10]=joints[1]; T[11]=joints[2]; }
        else {
            T[9]  = joints[jt*3+0] - joints[par*3+0];
            T[10] = joints[jt*3+1] - joints[par*3+1];
            T[11] = joints[jt*3+2] - joints[par*3+2];
        }
    }
    __syncthreads();

    if (tid < NP*NJ) {
        int p = tid / NJ, jt = tid - p*NJ;
        float shf[3];
#pragma unroll
        for (int k = 0; k < 3; k++)
            shf[k] = rdis[p*3+k] + 3.0f * tanhf(disp[p*3+k]);

        int chain[8], d = 0, a = jt;
        while (a >= 0) { chain[d++] = a; a = c_par[a]; }

        float G[12];
        {
            const float* Tr = sT + (p*NJ + chain[d-1])*12;
#pragma unroll
            for (int q = 0; q < 12; q++) G[q] = Tr[q];
        }
        for (int q = d - 2; q >= 0; q--) {
            const float* T = sT + (p*NJ + chain[q])*12;
            float N_[12];
#pragma unroll
            for (int i = 0; i < 3; i++) {
#pragma unroll
                for (int k = 0; k < 3; k++)
                    N_[i*3+k] = G[i*3]*T[k] + G[i*3+1]*T[3+k] + G[i*3+2]*T[6+k];
                N_[9+i] = G[i*3]*T[9] + G[i*3+1]*T[10] + G[i*3+2]*T[11] + G[9+i];
            }
#pragma unroll
            for (int q2 = 0; q2 < 12; q2++) G[q2] = N_[q2];
        }

        float jx = joints[jt*3], jy = joints[jt*3+1], jz = joints[jt*3+2];
#pragma unroll
        for (int i = 0; i < 3; i++) {
            float At = G[9+i] - (G[i*3]*jx + G[i*3+1]*jy + G[i*3+2]*jz) + shf[i];
            int n = 3*p + i;
            d_B[(4*jt + 0)*48 + n] = tf32r(G[i*3+0]);
            d_B[(4*jt + 1)*48 + n] = tf32r(G[i*3+1]);
            d_B[(4*jt + 2)*48 + n] = tf32r(G[i*3+2]);
            d_B[(4*jt + 3)*48 + n] = tf32r(At);
            out_joints[(p*NJ + jt)*3 + i] = G[9+i] + shf[i];
        }
    }
    if (tid < 192) d_B[92*48 + tid] = 0.f;   // zero-pad K rows 92..95
}

// ---------------------------------------------------------------------------
// Kernel 2: MMA skinning. CTA = 256 vertices, 8 warps x (2 m-frags, 6 n-frags).
// ---------------------------------------------------------------------------
__global__ void __launch_bounds__(256)
lbs_mma(const float* __restrict__ verts, const float* __restrict__ weights,
        float* __restrict__ out, int V)
{
    extern __shared__ float sm[];
    float* sB = sm + SB_OFF;
    float* sW = sm + SW_OFF;
    float* sD = sm;                    // aliases sB/sW after mainloop

    const int tid  = threadIdx.x;
    const int wid  = tid >> 5;
    const int lane = tid & 31;
    const int g    = lane >> 2;
    const int tig  = lane & 3;
    const int v0   = blockIdx.x * NT;

    // stage B (float4, 18 KB, L2-hot)
    for (int t = tid; t < 96*48/4; t += 256) {
        int row = t / 12, c4 = t - row*12;
        *(float4*)(sB + row*SBST + c4*4) = ((const float4*)d_B)[t];
    }
    // stage weights transposed: sW[j][v] (coalesced gmem, rows disjoint: SWST>=NT)
    {
        int nv = V - v0; if (nv > NT) nv = NT;
        for (int t = tid; t < NT*NJ; t += 256) {
            int v = t / NJ, j = t - v*NJ;
            sW[j*SWST + v] = (v < nv) ? weights[(size_t)(v0 + v)*NJ + j] : 0.f;
        }
    }
    __syncthreads();

    // vertex components for this lane's 4 rows (r0, r0+8, r0+16, r0+24)
    const int r0 = wid*32 + g;
    float comp[4];
#pragma unroll
    for (int q = 0; q < 4; q++) {
        int vg = v0 + r0 + 8*q;
        comp[q] = (tig == 3) ? 1.0f
                : (vg < V ? verts[(size_t)vg*3 + tig] : 0.f);
    }

    float acc[2][6][4];
#pragma unroll
    for (int m = 0; m < 2; m++)
#pragma unroll
        for (int f = 0; f < 6; f++)
#pragma unroll
            for (int q = 0; q < 4; q++) acc[m][f][q] = 0.f;

    const uint32_t* sBu = (const uint32_t*)sB;
#pragma unroll
    for (int s = 0; s < 12; s++) {
        int j0 = 2*s, j1 = 2*s + 1;
        float w0[4], w1[4];
#pragma unroll
        for (int q = 0; q < 4; q++) {
            w0[q] = sW[j0*SWST + r0 + 8*q];
            w1[q] = (j1 < NJ) ? sW[j1*SWST + r0 + 8*q] : 0.f;
        }
        uint32_t a[2][4];
#pragma unroll
        for (int m = 0; m < 2; m++) {
            a[m][0] = tf32u(w0[2*m]   * comp[2*m]);
            a[m][1] = tf32u(w0[2*m+1] * comp[2*m+1]);
            a[m][2] = tf32u(w1[2*m]   * comp[2*m]);
            a[m][3] = tf32u(w1[2*m+1] * comp[2*m+1]);
        }
        int kr0 = (8*s + tig)*SBST + g;
        int kr1 = kr0 + 4*SBST;
#pragma unroll
        for (int f = 0; f < 6; f++) {
            uint32_t b0 = sBu[kr0 + 8*f];
            uint32_t b1 = sBu[kr1 + 8*f];
            mma8(acc[0][f], a[0][0], a[0][1], a[0][2], a[0][3], b0, b1);
            mma8(acc[1][f], a[1][0], a[1][1], a[1][2], a[1][3], b0, b1);
        }
    }

    // stage D into smem (aliases sB/sW; conflict-free: bank = (8*tig+g)&31)
    __syncthreads();
#pragma unroll
    for (int m = 0; m < 2; m++) {
        int rA = r0 + 16*m, rB = rA + 8;
#pragma unroll
        for (int f = 0; f < 6; f++) {
            int n0 = 8*f + 2*tig;
            sD[ n0      *SDST + rA] = acc[m][f][0];
            sD[(n0 + 1) *SDST + rA] = acc[m][f][1];
            sD[ n0      *SDST + rB] = acc[m][f][2];
            sD[(n0 + 1) *SDST + rB] = acc[m][f][3];
        }
    }
    __syncthreads();

    // epilogue: warp wid -> poses 2wid, 2wid+1; lane = vertex; 12B-contig STG
#pragma unroll
    for (int pp = 0; pp < 2; pp++) {
        int p = wid*2 + pp;
#pragma unroll
        for (int c = 0; c < 8; c++) {
            int vl = c*32 + lane;
            int vg = v0 + vl;
            if (vg < V) {
                float o0 = sD[(3*p + 0)*SDST + vl];
                float o1 = sD[(3*p + 1)*SDST + vl];
                float o2 = sD[(3*p + 2)*SDST + vl];
                float* dst = out + ((size_t)p*V + vg)*3;
                dst[0] = o0; dst[1] = o1; dst[2] = o2;
            }
        }
    }
}

// ---------------------------------------------------------------------------
extern "C" void kernel_launch(void* const* d_in, const int* in_sizes, int n_in,
                              void* d_out, int out_size)
{
    const float* verts   = (const float*)d_in[0];
    const float* joints  = (const float*)d_in[1];
    const float* weights = (const float*)d_in[2];
    const float* disp    = (const float*)d_in[3];
    const float* rdis    = (const float*)d_in[4];

    int V = in_sizes[0] / 3;
    float* out = (float*)d_out;
    float* out_joints = out + (size_t)out_size - (size_t)NP * NJ * 3;

    cudaFuncSetAttribute(lbs_mma, cudaFuncAttributeMaxDynamicSharedMemorySize, SMEM_BYTES);

    pose_kernel<<<1, 384>>>(joints, disp, rdis,
                            (const float*)d_in[5],  (const float*)d_in[6],
                            (const float*)d_in[7],  (const float*)d_in[8],
                            (const float*)d_in[9],  (const float*)d_in[10],
                            (const float*)d_in[11], (const float*)d_in[12],
                            (const float*)d_in[13], (const float*)d_in[14],
                            (const float*)d_in[15],
                            out_joints);

    int blocks = (V + NT - 1) / NT;
    lbs_mma<<<blocks, 256, SMEM_BYTES>>>(verts, weights, out, V);
}